// round 16
// baseline (speedup 1.0000x reference)
#include <cuda_runtime.h>
#include <cuda_fp16.h>
#include <cstdint>

// Problem constants
#define Bz 2
#define Tz 2048
#define Cz 768
#define Hz 12
#define Dz 64
#define BHz (Bz*Hz)        // 24
#define Mz (Bz*Tz)         // 4096

typedef __half fp16;

// ---------------------------------------------------------------------------
// Scratch (static device arrays — no cudaMalloc allowed)
// ---------------------------------------------------------------------------
__device__ fp16 g_xf[(size_t)Mz * Cz];            // x, fp16
__device__ fp16 g_af[(size_t)Mz * Cz];            // attention out, fp16 [B,T,C]
__device__ fp16 g_w1[(size_t)1536 * Cz];          // W_att^T (k|v chunks), fp16
__device__ fp16 g_w2[(size_t)Cz * Cz];            // W_proj^T, fp16

// attention operands, [BH, T, D]
__device__ fp16 g_Kf[(size_t)BHz * Tz * Dz];
__device__ fp16 g_Qf[(size_t)BHz * Tz * Dz];      // rope(v) * 0.125 * log2(e)
__device__ fp16 g_Vf[(size_t)BHz * Tz * Dz];

// ---------------------------------------------------------------------------
// Warp-MMA + async-copy helpers (sm_80-compatible under plain sm_100 target)
// ---------------------------------------------------------------------------
__device__ __forceinline__ uint32_t smem_u32(const void* p) {
    uint32_t a;
    asm("{ .reg .u64 t; cvta.to.shared.u64 t, %1; cvt.u32.u64 %0, t; }"
        : "=r"(a) : "l"(p));
    return a;
}
__device__ __forceinline__ void mma_f16(float* d, const uint32_t* a,
                                        uint32_t b0, uint32_t b1) {
    asm volatile(
        "mma.sync.aligned.m16n8k16.row.col.f32.f16.f16.f32 "
        "{%0,%1,%2,%3}, {%4,%5,%6,%7}, {%8,%9}, {%0,%1,%2,%3};"
        : "+f"(d[0]), "+f"(d[1]), "+f"(d[2]), "+f"(d[3])
        : "r"(a[0]), "r"(a[1]), "r"(a[2]), "r"(a[3]), "r"(b0), "r"(b1));
}
__device__ __forceinline__ void ldmx4(uint32_t* r, uint32_t addr) {
    asm volatile("ldmatrix.sync.aligned.m8n8.x4.shared.b16 {%0,%1,%2,%3}, [%4];"
        : "=r"(r[0]), "=r"(r[1]), "=r"(r[2]), "=r"(r[3]) : "r"(addr));
}
__device__ __forceinline__ void ldmx4t(uint32_t* r, uint32_t addr) {
    asm volatile("ldmatrix.sync.aligned.m8n8.x4.trans.shared.b16 {%0,%1,%2,%3}, [%4];"
        : "=r"(r[0]), "=r"(r[1]), "=r"(r[2]), "=r"(r[3]) : "r"(addr));
}
__device__ __forceinline__ void cpa16(uint32_t d, const void* s) {
    asm volatile("cp.async.cg.shared.global [%0], [%1], 16;" :: "r"(d), "l"(s));
}
#define CP_COMMIT() asm volatile("cp.async.commit_group;" ::: "memory")
#define CP_WAIT(n)  asm volatile("cp.async.wait_group %0;" :: "n"(n) : "memory")

__device__ __forceinline__ uint32_t packh2(float lo, float hi) {
    __half2 h = __floats2half2_rn(lo, hi);
    return *reinterpret_cast<uint32_t*>(&h);
}
// raw ex2.approx (exp2) — single MUFU op
__device__ __forceinline__ float ex2(float x) {
    float y;
    asm("ex2.approx.ftz.f32 %0, %1;" : "=f"(y) : "f"(x));
    return y;
}

// ---------------------------------------------------------------------------
// Merged prep kernel: z=0 -> W_att transpose (k|v remap), z=1 -> W_proj
// transpose, z=2 -> x fp16 conversion (grid-stride).
// grid (48, 24, 3) x 256 threads.
// ---------------------------------------------------------------------------
__global__ __launch_bounds__(256) void prep_kernel(
    const float* __restrict__ x, fp16* __restrict__ xf,
    const float* __restrict__ W1, fp16* __restrict__ out1,
    const float* __restrict__ W2, fp16* __restrict__ out2)
{
    int z = blockIdx.z;
    if (z == 2) {
        int idx = (blockIdx.x + 48 * blockIdx.y) * 256 + threadIdx.x;
        const int stride = 48 * 24 * 256;
        for (int i = idx; i < Mz * Cz; i += stride)
            xf[i] = __float2half_rn(x[i]);
        return;
    }
    __shared__ float t[32][33];
    int tx = threadIdx.x & 31, ty = threadIdx.x >> 5;
    int N = z ? Cz : 1536;
    int ldw = z ? Cz : 3 * Cz;
    if ((int)blockIdx.x * 32 >= N) return;
    const float* W = z ? W2 : W1;
    fp16* out = z ? out2 : out1;

    int n0 = blockIdx.x * 32;
    int k0 = blockIdx.y * 32;
    int col0 = n0 + ((!z && n0 >= 768) ? 768 : 0);   // v-chunk remap for W_att

    #pragma unroll
    for (int i = 0; i < 4; i++) {
        int k = k0 + ty + i * 8;
        t[ty + i * 8][tx] = W[(size_t)k * ldw + col0 + tx];
    }
    __syncthreads();
    #pragma unroll
    for (int i = 0; i < 4; i++) {
        int n = n0 + ty + i * 8;
        out[(size_t)n * Cz + k0 + tx] = __float2half_rn(t[tx][ty + i * 8]);
    }
}

// ---------------------------------------------------------------------------
// Dense GEMM via mma.sync fp16, single-pass, 3-stage cp.async, one sync/chunk.
// C[M,N] = A[M,K] @ Bt[N,K]^T. 128x128x32 CTA, 8 warps, 2 CTAs/SM.
// MODE 1 epilogue = fused RoPE + fp16 prep (QKV). Q scale folds log2(e).
// ---------------------------------------------------------------------------
#define MG_STRIDE 80            // 32 fp16 = 64B data + 16B pad
#define MG_A  0
#define MG_B  10240
#define MG_STAGE 20480
#define MG_SMEM (3 * MG_STAGE)  // 61440 -> 2 CTAs/SM

__global__ __launch_bounds__(256, 2) void mm_gemm_kernel(
    const fp16* __restrict__ Af, const fp16* __restrict__ Bf,
    const float* __restrict__ cosb, const float* __restrict__ sinb,
    fp16* __restrict__ Kf, fp16* __restrict__ Qf, fp16* __restrict__ Vf,
    int K)
{
    extern __shared__ __align__(16) char gsm[];
    const uint32_t smb = smem_u32(gsm);
    const int tid  = threadIdx.x;
    const int w    = tid >> 5;
    const int lane = tid & 31;
    const int n0 = blockIdx.x * 128;
    const int m0 = blockIdx.y * 128;
    const int wm = w & 3;
    const int wn = w >> 2;

    auto load_stage = [&](int s, int kc) {
        uint32_t base = smb + s * MG_STAGE;
        #pragma unroll
        for (int it = 0; it < 2; it++) {
            int u   = tid + it * 256;
            int row = u >> 2, cc = u & 3;
            size_t ga = (size_t)(m0 + row) * K + kc + cc * 8;
            size_t gb = (size_t)(n0 + row) * K + kc + cc * 8;
            uint32_t off = (uint32_t)(row * MG_STRIDE + cc * 16);
            cpa16(base + MG_A + off, Af + ga);
            cpa16(base + MG_B + off, Bf + gb);
        }
    };

    float acc[2][8][4];
    #pragma unroll
    for (int a = 0; a < 2; a++)
        #pragma unroll
        for (int b = 0; b < 8; b++)
            #pragma unroll
            for (int c = 0; c < 4; c++) acc[a][b][c] = 0.f;

    const int arow = lane & 15, asel = lane >> 4;
    const int brow = lane & 7,  bsel = (lane >> 3) & 3;
    const int nch = K / 32;

    load_stage(0, 0);  CP_COMMIT();
    load_stage(1, 32); CP_COMMIT();

    int buf = 0, nbuf = 2;
    for (int c = 0; c < nch; c++) {
        CP_WAIT(1);
        __syncthreads();
        if (c + 2 < nch) load_stage(nbuf, (c + 2) * 32);
        CP_COMMIT();

        const uint32_t sb = smb + buf * MG_STAGE;

        uint32_t af[2][2][4];
        uint32_t bq[4][4];

        #pragma unroll
        for (int ma = 0; ma < 2; ma++)
            #pragma unroll
            for (int ks = 0; ks < 2; ks++)
                ldmx4(af[ma][ks], sb + MG_A +
                      (uint32_t)((wm * 32 + ma * 16 + arow) * MG_STRIDE + ks * 32 + asel * 16));
        #pragma unroll
        for (int half = 0; half < 2; half++) {
            #pragma unroll
            for (int q = 0; q < 4; q++)
                ldmx4(bq[q], sb + MG_B +
                      (uint32_t)((wn * 64 + (half * 4 + q) * 8 + brow) * MG_STRIDE + bsel * 16));
            #pragma unroll
            for (int ks = 0; ks < 2; ks++)
                #pragma unroll
                for (int q = 0; q < 4; q++)
                    #pragma unroll
                    for (int ma = 0; ma < 2; ma++)
                        mma_f16(acc[ma][half * 4 + q], af[ma][ks], bq[q][2 * ks], bq[q][2 * ks + 1]);
        }

        buf  = (buf == 2)  ? 0 : buf + 1;
        nbuf = (nbuf == 2) ? 0 : nbuf + 1;
    }

    const int rg = lane >> 2, cg = lane & 3;

    // Fused RoPE epilogue. Whole CTA is k-chunk or v-chunk (n0 aligned to 768).
    const bool isv = (n0 >= 768);
    const float scale = 0.125f * 1.4426950408889634f;  // D^-0.5 * log2(e)
    #pragma unroll
    for (int ma = 0; ma < 2; ma++) {
        int row = m0 + wm * 32 + ma * 16 + rg;   // = b*T + t
        int b  = row >> 11;
        int t0 = row & (Tz - 1);
        int t1 = t0 + 8;
        #pragma unroll
        for (int na = 0; na < 8; na++) {
            int col = n0 + wn * 64 + na * 8 + 2 * cg;
            int ch  = isv ? col - 768 : col;
            int h   = ch >> 6;
            int d   = ch & 63;
            int i   = d >> 1;
            float c0 = cosb[t0 * 32 + i], s0 = sinb[t0 * 32 + i];
            float c1 = cosb[t1 * 32 + i], s1 = sinb[t1 * 32 + i];
            size_t o0 = ((size_t)(b * Hz + h) * Tz + t0) * Dz + d;
            size_t o1 = ((size_t)(b * Hz + h) * Tz + t1) * Dz + d;
            float v0 = acc[ma][na][0], v1 = acc[ma][na][1];
            float v2 = acc[ma][na][2], v3 = acc[ma][na][3];
            if (!isv) {
                *reinterpret_cast<uint32_t*>(Kf + o0) =
                    packh2(v0 * c0 - v1 * s0, v0 * s0 + v1 * c0);
                *reinterpret_cast<uint32_t*>(Kf + o1) =
                    packh2(v2 * c1 - v3 * s1, v2 * s1 + v3 * c1);
            } else {
                *reinterpret_cast<uint32_t*>(Qf + o0) =
                    packh2((v0 * c0 - v1 * s0) * scale, (v0 * s0 + v1 * c0) * scale);
                *reinterpret_cast<uint32_t*>(Qf + o1) =
                    packh2((v2 * c1 - v3 * s1) * scale, (v2 * s1 + v3 * c1) * scale);
                *reinterpret_cast<uint32_t*>(Vf + o0) = packh2(v0, v1);
                *reinterpret_cast<uint32_t*>(Vf + o1) = packh2(v2, v3);
            }
        }
    }
}

// ---------------------------------------------------------------------------
// Proj GEMM: 64x128 CTA tiles for full-chip load balance (grid 6x64=384).
// 8 warps = 4 row-strips(16) x 2 col-strips(64). Same 3-stage pipeline and
// same per-accumulator K-chunk order as the 128-tile kernel (bit-identical).
// ---------------------------------------------------------------------------
#define M6_STRIDE 80
#define M6_A  0
#define M6_B  5120               // A: 64*80
#define M6_STAGE 15360           // + B: 128*80
#define M6_SMEM (3 * M6_STAGE)   // 46080 -> 2 CTAs/SM

__global__ __launch_bounds__(256, 2) void mm_gemm64_kernel(
    const fp16* __restrict__ Af, const fp16* __restrict__ Bf,
    float* __restrict__ Cmat, const float* __restrict__ bias,
    int K, int ldc)
{
    extern __shared__ __align__(16) char gsm6[];
    const uint32_t smb = smem_u32(gsm6);
    const int tid  = threadIdx.x;
    const int w    = tid >> 5;
    const int lane = tid & 31;
    const int n0 = blockIdx.x * 128;
    const int m0 = blockIdx.y * 64;
    const int wm = w & 3;        // 16-row strip
    const int wn = w >> 2;       // 64-col strip

    auto load_stage = [&](int s, int kc) {
        uint32_t base = smb + s * M6_STAGE;
        {   // A: 64 rows x 4 units = 256
            int row = tid >> 2, cc = tid & 3;
            cpa16(base + M6_A + (uint32_t)(row * M6_STRIDE + cc * 16),
                  Af + (size_t)(m0 + row) * K + kc + cc * 8);
        }
        #pragma unroll
        for (int it = 0; it < 2; it++) {   // B: 128 rows x 4 units = 512
            int u = tid + it * 256;
            int row = u >> 2, cc = u & 3;
            cpa16(base + M6_B + (uint32_t)(row * M6_STRIDE + cc * 16),
                  Bf + (size_t)(n0 + row) * K + kc + cc * 8);
        }
    };

    float acc[8][4];
    #pragma unroll
    for (int b = 0; b < 8; b++)
        #pragma unroll
        for (int c = 0; c < 4; c++) acc[b][c] = 0.f;

    const int arow = lane & 15, asel = lane >> 4;
    const int brow = lane & 7,  bsel = (lane >> 3) & 3;
    const int nch = K / 32;

    load_stage(0, 0);  CP_COMMIT();
    load_stage(1, 32); CP_COMMIT();

    int buf = 0, nbuf = 2;
    for (int c = 0; c < nch; c++) {
        CP_WAIT(1);
        __syncthreads();
        if (c + 2 < nch) load_stage(nbuf, (c + 2) * 32);
        CP_COMMIT();

        const uint32_t sb = smb + buf * M6_STAGE;

        uint32_t af[2][4];
        uint32_t bq[4][4];

        #pragma unroll
        for (int ks = 0; ks < 2; ks++)
            ldmx4(af[ks], sb + M6_A +
                  (uint32_t)((wm * 16 + arow) * M6_STRIDE + ks * 32 + asel * 16));
        #pragma unroll
        for (int half = 0; half < 2; half++) {
            #pragma unroll
            for (int q = 0; q < 4; q++)
                ldmx4(bq[q], sb + M6_B +
                      (uint32_t)((wn * 64 + (half * 4 + q) * 8 + brow) * M6_STRIDE + bsel * 16));
            #pragma unroll
            for (int ks = 0; ks < 2; ks++)
                #pragma unroll
                for (int q = 0; q < 4; q++)
                    mma_f16(acc[half * 4 + q], af[ks], bq[q][2 * ks], bq[q][2 * ks + 1]);
        }

        buf  = (buf == 2)  ? 0 : buf + 1;
        nbuf = (nbuf == 2) ? 0 : nbuf + 1;
    }

    const int rg = lane >> 2, cg = lane & 3;
    int row = m0 + wm * 16 + rg;
    #pragma unroll
    for (int na = 0; na < 8; na++) {
        int col = n0 + wn * 64 + na * 8 + 2 * cg;
        float b0 = bias ? bias[col] : 0.f;
        float b1 = bias ? bias[col + 1] : 0.f;
        *reinterpret_cast<float2*>(Cmat + (size_t)row * ldc + col) =
            make_float2(acc[na][0] + b0, acc[na][1] + b1);
        *reinterpret_cast<float2*>(Cmat + (size_t)(row + 8) * ldc + col) =
            make_float2(acc[na][2] + b0, acc[na][3] + b1);
    }
}

// ---------------------------------------------------------------------------
// Flash attention v10: 3-stage cp.async KV pipeline, single sync per iter.
// exp2-domain softmax, MMA row-sums. 128 q-rows, 8 warps x 16 q-rows.
// ---------------------------------------------------------------------------
#define FX_STRIDE 144                 // 64 fp16 = 128B + 16B pad
#define FX_TILE   (128 * FX_STRIDE)   // 18432
#define FX_STAGE  (2 * FX_TILE)       // KF,VF = 36864
#define FX_Q      (3 * FX_STAGE)      // 110592
#define FX_SMEM   (FX_Q + FX_TILE)    // 129024

__global__ __launch_bounds__(256, 1) void flash10_kernel(
    const fp16* __restrict__ Qf, const fp16* __restrict__ Kf,
    const fp16* __restrict__ Vf, fp16* __restrict__ Of)
{
    extern __shared__ __align__(16) char smx[];
    const uint32_t smb = smem_u32(smx);
    const int tid  = threadIdx.x;
    const int w    = tid >> 5;
    const int lane = tid & 31;
    const int qt   = (int)gridDim.x - 1 - (int)blockIdx.x;   // heavy tiles first
    const int bh   = blockIdx.y;
    const size_t hb = (size_t)bh * Tz * Dz;
    const uint32_t ONES = 0x3C003C00u;   // fp16 {1,1}

    auto load_kv = [&](int s, int j) {
        uint32_t base = smb + s * FX_STAGE;
        const size_t kb = hb + (size_t)j * 128 * 64;
        #pragma unroll
        for (int it = 0; it < 4; it++) {
            int u = tid + it * 256;
            int row = u >> 3, cc = u & 7;
            uint32_t off = (uint32_t)(row * FX_STRIDE + cc * 16);
            size_t g = kb + row * 64 + cc * 8;
            cpa16(base + 0 * FX_TILE + off, Kf + g);
            cpa16(base + 1 * FX_TILE + off, Vf + g);
        }
    };

    load_kv(0, 0);
    CP_COMMIT();
    if (qt >= 1) load_kv(1, 1);
    CP_COMMIT();
    {
        const fp16* qsrc = Qf + hb + (size_t)qt * 128 * 64;
        #pragma unroll
        for (int it = 0; it < 4; it++) {
            int u = tid + it * 256;
            int row = u >> 3, cc = u & 7;
            *reinterpret_cast<uint4*>(smx + FX_Q + row * FX_STRIDE + cc * 16) =
                *reinterpret_cast<const uint4*>(qsrc + row * 64 + cc * 8);
        }
    }
    __syncthreads();

    uint32_t qf[16];
    {
        int arow = lane & 15, asel = lane >> 4;
        #pragma unroll
        for (int ka = 0; ka < 4; ka++)
            ldmx4(qf + ka * 4, smb + FX_Q +
                  (uint32_t)((16 * w + arow) * FX_STRIDE + ka * 32 + asel * 16));
    }

    float o[8][4];
    #pragma unroll
    for (int nv = 0; nv < 8; nv++)
        #pragma unroll
        for (int c = 0; c < 4; c++) o[nv][c] = 0.f;
    float mA = -1e30f, mB = -1e30f, lA = 0.f, lB = 0.f;

    const int rg = lane >> 2, cg = lane & 3;
    const int brow = lane & 7, bsel = (lane >> 3) & 3;
    const int vkey = lane & 15, vsel = lane >> 4;

    int buf = 0, nbuf = 2;
    for (int jt = 0; jt <= qt; jt++) {
        CP_WAIT(1);
        __syncthreads();                       // stage jt ready; all warps past jt-1
        if (jt + 2 <= qt) load_kv(nbuf, jt + 2);
        CP_COMMIT();                           // uniform group numbering

        const uint32_t sb = smb + buf * FX_STAGE;

        // ---- S = Q@K^T (log2 domain), single-pass fp16 ----
        float s[16][4];
        #pragma unroll
        for (int na = 0; na < 16; na++)
            #pragma unroll
            for (int c = 0; c < 4; c++) s[na][c] = 0.f;

        #pragma unroll
        for (int kp = 0; kp < 2; kp++) {
            #pragma unroll
            for (int half = 0; half < 2; half++) {
                uint32_t kf[8][4];
                #pragma unroll
                for (int q = 0; q < 8; q++)
                    ldmx4(kf[q], sb +
                          (uint32_t)(((half * 8 + q) * 8 + brow) * FX_STRIDE + kp * 64 + bsel * 16));
                #pragma unroll
                for (int j = 0; j < 2; j++)
                    #pragma unroll
                    for (int q = 0; q < 8; q++)
                        mma_f16(s[half * 8 + q], qf + (2 * kp + j) * 4, kf[q][2 * j], kf[q][2 * j + 1]);
            }
        }

        // ---- causal mask (diagonal tile) ----
        if (jt == qt) {
            int rA = 16 * w + rg, rB = rA + 8;
            #pragma unroll
            for (int na = 0; na < 16; na++) {
                int c0 = 8 * na + 2 * cg;
                if (c0 > rA)     s[na][0] = -1e30f;
                if (c0 + 1 > rA) s[na][1] = -1e30f;
                if (c0 > rB)     s[na][2] = -1e30f;
                if (c0 + 1 > rB) s[na][3] = -1e30f;
            }
        }

        // ---- online softmax: row maxes + rescale (log2 domain) ----
        float xA = -1e30f, xB = -1e30f;
        #pragma unroll
        for (int na = 0; na < 16; na++) {
            xA = fmaxf(xA, fmaxf(s[na][0], s[na][1]));
            xB = fmaxf(xB, fmaxf(s[na][2], s[na][3]));
        }
        xA = fmaxf(xA, __shfl_xor_sync(0xffffffffu, xA, 1));
        xA = fmaxf(xA, __shfl_xor_sync(0xffffffffu, xA, 2));
        xB = fmaxf(xB, __shfl_xor_sync(0xffffffffu, xB, 1));
        xB = fmaxf(xB, __shfl_xor_sync(0xffffffffu, xB, 2));
        float nmA = fmaxf(mA, xA), nmB = fmaxf(mB, xB);
        float cA = ex2(mA - nmA), cB = ex2(mB - nmB);
        mA = nmA; mB = nmB;
        #pragma unroll
        for (int nv = 0; nv < 8; nv++) {
            o[nv][0] *= cA; o[nv][1] *= cA;
            o[nv][2] *= cB; o[nv][3] *= cB;
        }

        // ---- PV: exp2 -> fp16 P; V mma; row-sums via ones-MMA ----
        float lacc[4] = {0.f, 0.f, 0.f, 0.f};
        #pragma unroll
        for (int ka = 0; ka < 8; ka++) {
            float e00 = ex2(s[2 * ka][0] - nmA);
            float e01 = ex2(s[2 * ka][1] - nmA);
            float e02 = ex2(s[2 * ka][2] - nmB);
            float e03 = ex2(s[2 * ka][3] - nmB);
            float e10 = ex2(s[2 * ka + 1][0] - nmA);
            float e11 = ex2(s[2 * ka + 1][1] - nmA);
            float e12 = ex2(s[2 * ka + 1][2] - nmB);
            float e13 = ex2(s[2 * ka + 1][3] - nmB);

            uint32_t p4[4];
            p4[0] = packh2(e00, e01);
            p4[1] = packh2(e02, e03);
            p4[2] = packh2(e10, e11);
            p4[3] = packh2(e12, e13);

            mma_f16(lacc, p4, ONES, ONES);   // row sums of quantized P

            uint32_t vf[4][4];
            #pragma unroll
            for (int nv = 0; nv < 4; nv++)
                ldmx4t(vf[nv], sb + 1 * FX_TILE +
                       (uint32_t)((ka * 16 + vkey) * FX_STRIDE + (nv * 16 + vsel * 8) * 2));
            #pragma unroll
            for (int nv = 0; nv < 4; nv++) {
                mma_f16(o[2 * nv],     p4, vf[nv][0], vf[nv][1]);
                mma_f16(o[2 * nv + 1], p4, vf[nv][2], vf[nv][3]);
            }
        }
        lA = lA * cA + lacc[0];
        lB = lB * cB + lacc[2];

        buf  = (buf == 2)  ? 0 : buf + 1;
        nbuf = (nbuf == 2) ? 0 : nbuf + 1;
    }

    // ---- normalize + write fp16 [B,T,C] ----
    const int b = bh / Hz, h = bh % Hz;
    const float invA = 1.f / lA, invB = 1.f / lB;
    int rA = qt * 128 + 16 * w + rg;
    #pragma unroll
    for (int nv = 0; nv < 8; nv++) {
        int col = h * 64 + nv * 8 + 2 * cg;
        size_t baseA = (size_t)(b * Tz + rA) * Cz + col;
        size_t baseB = (size_t)(b * Tz + rA + 8) * Cz + col;
        *reinterpret_cast<uint32_t*>(Of + baseA) =
            packh2(o[nv][0] * invA, o[nv][1] * invA);
        *reinterpret_cast<uint32_t*>(Of + baseB) =
            packh2(o[nv][2] * invB, o[nv][3] * invB);
    }
}

// ---------------------------------------------------------------------------
// kernel_launch
// ---------------------------------------------------------------------------
extern "C" void kernel_launch(void* const* d_in, const int* in_sizes, int n_in,
                              void* d_out, int out_size)
{
    const float* x      = (const float*)d_in[0];
    const float* cosb   = (const float*)d_in[1];
    const float* sinb   = (const float*)d_in[2];
    const float* W_att  = (const float*)d_in[3];
    const float* W_proj = (const float*)d_in[4];
    const float* b_proj = (const float*)d_in[5];
    float* out = (float*)d_out;

    fp16 *xf, *af, *w1, *w2, *Kfp, *Qfp, *Vfp;
    cudaGetSymbolAddress((void**)&xf,  g_xf);
    cudaGetSymbolAddress((void**)&af,  g_af);
    cudaGetSymbolAddress((void**)&w1,  g_w1);
    cudaGetSymbolAddress((void**)&w2,  g_w2);
    cudaGetSymbolAddress((void**)&Kfp, g_Kf);
    cudaGetSymbolAddress((void**)&Qfp, g_Qf);
    cudaGetSymbolAddress((void**)&Vfp, g_Vf);

    cudaFuncSetAttribute(mm_gemm_kernel,
                         cudaFuncAttributeMaxDynamicSharedMemorySize, MG_SMEM);
    cudaFuncSetAttribute(mm_gemm64_kernel,
                         cudaFuncAttributeMaxDynamicSharedMemorySize, M6_SMEM);
    cudaFuncSetAttribute(flash10_kernel,
                         cudaFuncAttributeMaxDynamicSharedMemorySize, FX_SMEM);

    // prep: merged x-conv + weight transposes (one launch)
    prep_kernel<<<dim3(48, Cz / 32, 3), 256>>>(x, xf, W_att, w1, W_proj, w2);

    // 1) QKV GEMM + fused RoPE epilogue -> Kf / Qf / Vf  [BH,T,D]
    mm_gemm_kernel<<<dim3(1536 / 128, Mz / 128), 256, MG_SMEM>>>(
        xf, w1, cosb, sinb, Kfp, Qfp, Vfp, Cz);

    // 2) Flash attention (3-stage pipeline, single sync/iter) -> af fp16
    flash10_kernel<<<dim3(Tz / 128, BHz), 256, FX_SMEM>>>(
        Qfp, Kfp, Vfp, af);

    // 3) proj GEMM + bias -> d_out  (64-row tiles: grid 6x64 = full chip)
    mm_gemm64_kernel<<<dim3(Cz / 128, Mz / 64), 256, M6_SMEM>>>(
        af, w2, out, b_proj, Cz, Cz);
}

// round 17
// speedup vs baseline: 1.0683x; 1.0683x over previous
#include <cuda_runtime.h>
#include <cuda_fp16.h>
#include <cstdint>

// Problem constants
#define Bz 2
#define Tz 2048
#define Cz 768
#define Hz 12
#define Dz 64
#define BHz (Bz*Hz)        // 24
#define Mz (Bz*Tz)         // 4096

typedef __half fp16;

// ---------------------------------------------------------------------------
// Scratch (static device arrays — no cudaMalloc allowed)
// ---------------------------------------------------------------------------
__device__ fp16 g_xf[(size_t)Mz * Cz];            // x, fp16
__device__ fp16 g_af[(size_t)Mz * Cz];            // attention out, fp16 [B,T,C]
__device__ fp16 g_w1[(size_t)1536 * Cz];          // W_att^T (k|v chunks), fp16
__device__ fp16 g_w2[(size_t)Cz * Cz];            // W_proj^T, fp16

// attention operands, [BH, T, D]
__device__ fp16 g_Kf[(size_t)BHz * Tz * Dz];
__device__ fp16 g_Qf[(size_t)BHz * Tz * Dz];      // rope(v) * 0.125 * log2(e)
__device__ fp16 g_Vf[(size_t)BHz * Tz * Dz];

// ---------------------------------------------------------------------------
// Warp-MMA + async-copy helpers (sm_80-compatible under plain sm_100 target)
// ---------------------------------------------------------------------------
__device__ __forceinline__ uint32_t smem_u32(const void* p) {
    uint32_t a;
    asm("{ .reg .u64 t; cvta.to.shared.u64 t, %1; cvt.u32.u64 %0, t; }"
        : "=r"(a) : "l"(p));
    return a;
}
__device__ __forceinline__ void mma_f16(float* d, const uint32_t* a,
                                        uint32_t b0, uint32_t b1) {
    asm volatile(
        "mma.sync.aligned.m16n8k16.row.col.f32.f16.f16.f32 "
        "{%0,%1,%2,%3}, {%4,%5,%6,%7}, {%8,%9}, {%0,%1,%2,%3};"
        : "+f"(d[0]), "+f"(d[1]), "+f"(d[2]), "+f"(d[3])
        : "r"(a[0]), "r"(a[1]), "r"(a[2]), "r"(a[3]), "r"(b0), "r"(b1));
}
__device__ __forceinline__ void ldmx4(uint32_t* r, uint32_t addr) {
    asm volatile("ldmatrix.sync.aligned.m8n8.x4.shared.b16 {%0,%1,%2,%3}, [%4];"
        : "=r"(r[0]), "=r"(r[1]), "=r"(r[2]), "=r"(r[3]) : "r"(addr));
}
__device__ __forceinline__ void ldmx4t(uint32_t* r, uint32_t addr) {
    asm volatile("ldmatrix.sync.aligned.m8n8.x4.trans.shared.b16 {%0,%1,%2,%3}, [%4];"
        : "=r"(r[0]), "=r"(r[1]), "=r"(r[2]), "=r"(r[3]) : "r"(addr));
}
__device__ __forceinline__ void cpa16(uint32_t d, const void* s) {
    asm volatile("cp.async.cg.shared.global [%0], [%1], 16;" :: "r"(d), "l"(s));
}
#define CP_COMMIT() asm volatile("cp.async.commit_group;" ::: "memory")
#define CP_WAIT(n)  asm volatile("cp.async.wait_group %0;" :: "n"(n) : "memory")

__device__ __forceinline__ uint32_t packh2(float lo, float hi) {
    __half2 h = __floats2half2_rn(lo, hi);
    return *reinterpret_cast<uint32_t*>(&h);
}
// raw ex2.approx (exp2) — single MUFU op
__device__ __forceinline__ float ex2(float x) {
    float y;
    asm("ex2.approx.ftz.f32 %0, %1;" : "=f"(y) : "f"(x));
    return y;
}

// ---------------------------------------------------------------------------
// Merged prep kernel: z=0 -> W_att transpose (k|v remap), z=1 -> W_proj
// transpose, z=2 -> x fp16 conversion (grid-stride).
// grid (48, 24, 3) x 256 threads.
// ---------------------------------------------------------------------------
__global__ __launch_bounds__(256) void prep_kernel(
    const float* __restrict__ x, fp16* __restrict__ xf,
    const float* __restrict__ W1, fp16* __restrict__ out1,
    const float* __restrict__ W2, fp16* __restrict__ out2)
{
    int z = blockIdx.z;
    if (z == 2) {
        int idx = (blockIdx.x + 48 * blockIdx.y) * 256 + threadIdx.x;
        const int stride = 48 * 24 * 256;
        for (int i = idx; i < Mz * Cz; i += stride)
            xf[i] = __float2half_rn(x[i]);
        return;
    }
    __shared__ float t[32][33];
    int tx = threadIdx.x & 31, ty = threadIdx.x >> 5;
    int N = z ? Cz : 1536;
    int ldw = z ? Cz : 3 * Cz;
    if ((int)blockIdx.x * 32 >= N) return;
    const float* W = z ? W2 : W1;
    fp16* out = z ? out2 : out1;

    int n0 = blockIdx.x * 32;
    int k0 = blockIdx.y * 32;
    int col0 = n0 + ((!z && n0 >= 768) ? 768 : 0);   // v-chunk remap for W_att

    #pragma unroll
    for (int i = 0; i < 4; i++) {
        int k = k0 + ty + i * 8;
        t[ty + i * 8][tx] = W[(size_t)k * ldw + col0 + tx];
    }
    __syncthreads();
    #pragma unroll
    for (int i = 0; i < 4; i++) {
        int n = n0 + ty + i * 8;
        out[(size_t)n * Cz + k0 + tx] = __float2half_rn(t[tx][ty + i * 8]);
    }
}

// ---------------------------------------------------------------------------
// Dense GEMM via mma.sync fp16, single-pass, 3-stage cp.async, one sync/chunk.
// C[M,N] = A[M,K] @ Bt[N,K]^T. 128x128x32 CTA, 8 warps, 2 CTAs/SM.
// MODE 0: epilogue = fp32 C + bias (proj).
// MODE 1: epilogue = fused RoPE + fp16 prep (QKV). Q scale folds log2(e).
// ---------------------------------------------------------------------------
#define MG_STRIDE 80            // 32 fp16 = 64B data + 16B pad
#define MG_A  0
#define MG_B  10240
#define MG_STAGE 20480
#define MG_SMEM (3 * MG_STAGE)  // 61440 -> 2 CTAs/SM

template<int MODE>
__global__ __launch_bounds__(256, 2) void mm_gemm_kernel(
    const fp16* __restrict__ Af, const fp16* __restrict__ Bf,
    float* __restrict__ Cmat, const float* __restrict__ bias,
    const float* __restrict__ cosb, const float* __restrict__ sinb,
    fp16* __restrict__ Kf, fp16* __restrict__ Qf, fp16* __restrict__ Vf,
    int K, int ldc)
{
    extern __shared__ __align__(16) char gsm[];
    const uint32_t smb = smem_u32(gsm);
    const int tid  = threadIdx.x;
    const int w    = tid >> 5;
    const int lane = tid & 31;
    const int n0 = blockIdx.x * 128;
    const int m0 = blockIdx.y * 128;
    const int wm = w & 3;
    const int wn = w >> 2;

    auto load_stage = [&](int s, int kc) {
        uint32_t base = smb + s * MG_STAGE;
        #pragma unroll
        for (int it = 0; it < 2; it++) {
            int u   = tid + it * 256;
            int row = u >> 2, cc = u & 3;
            size_t ga = (size_t)(m0 + row) * K + kc + cc * 8;
            size_t gb = (size_t)(n0 + row) * K + kc + cc * 8;
            uint32_t off = (uint32_t)(row * MG_STRIDE + cc * 16);
            cpa16(base + MG_A + off, Af + ga);
            cpa16(base + MG_B + off, Bf + gb);
        }
    };

    float acc[2][8][4];
    #pragma unroll
    for (int a = 0; a < 2; a++)
        #pragma unroll
        for (int b = 0; b < 8; b++)
            #pragma unroll
            for (int c = 0; c < 4; c++) acc[a][b][c] = 0.f;

    const int arow = lane & 15, asel = lane >> 4;
    const int brow = lane & 7,  bsel = (lane >> 3) & 3;
    const int nch = K / 32;

    load_stage(0, 0);  CP_COMMIT();
    load_stage(1, 32); CP_COMMIT();

    int buf = 0, nbuf = 2;
    for (int c = 0; c < nch; c++) {
        CP_WAIT(1);
        __syncthreads();
        if (c + 2 < nch) load_stage(nbuf, (c + 2) * 32);
        CP_COMMIT();

        const uint32_t sb = smb + buf * MG_STAGE;

        uint32_t af[2][2][4];
        uint32_t bq[4][4];

        #pragma unroll
        for (int ma = 0; ma < 2; ma++)
            #pragma unroll
            for (int ks = 0; ks < 2; ks++)
                ldmx4(af[ma][ks], sb + MG_A +
                      (uint32_t)((wm * 32 + ma * 16 + arow) * MG_STRIDE + ks * 32 + asel * 16));
        #pragma unroll
        for (int half = 0; half < 2; half++) {
            #pragma unroll
            for (int q = 0; q < 4; q++)
                ldmx4(bq[q], sb + MG_B +
                      (uint32_t)((wn * 64 + (half * 4 + q) * 8 + brow) * MG_STRIDE + bsel * 16));
            #pragma unroll
            for (int ks = 0; ks < 2; ks++)
                #pragma unroll
                for (int q = 0; q < 4; q++)
                    #pragma unroll
                    for (int ma = 0; ma < 2; ma++)
                        mma_f16(acc[ma][half * 4 + q], af[ma][ks], bq[q][2 * ks], bq[q][2 * ks + 1]);
        }

        buf  = (buf == 2)  ? 0 : buf + 1;
        nbuf = (nbuf == 2) ? 0 : nbuf + 1;
    }

    const int rg = lane >> 2, cg = lane & 3;

    if (MODE == 0) {
        #pragma unroll
        for (int ma = 0; ma < 2; ma++) {
            int row = m0 + wm * 32 + ma * 16 + rg;
            #pragma unroll
            for (int na = 0; na < 8; na++) {
                int col = n0 + wn * 64 + na * 8 + 2 * cg;
                float b0 = bias ? bias[col] : 0.f;
                float b1 = bias ? bias[col + 1] : 0.f;
                *reinterpret_cast<float2*>(Cmat + (size_t)row * ldc + col) =
                    make_float2(acc[ma][na][0] + b0, acc[ma][na][1] + b1);
                *reinterpret_cast<float2*>(Cmat + (size_t)(row + 8) * ldc + col) =
                    make_float2(acc[ma][na][2] + b0, acc[ma][na][3] + b1);
            }
        }
    } else {
        // Fused RoPE epilogue. Whole CTA is k-chunk or v-chunk (n0 aligned to 768).
        const bool isv = (n0 >= 768);
        const float scale = 0.125f * 1.4426950408889634f;  // D^-0.5 * log2(e)
        #pragma unroll
        for (int ma = 0; ma < 2; ma++) {
            int row = m0 + wm * 32 + ma * 16 + rg;   // = b*T + t
            int b  = row >> 11;
            int t0 = row & (Tz - 1);
            int t1 = t0 + 8;
            #pragma unroll
            for (int na = 0; na < 8; na++) {
                int col = n0 + wn * 64 + na * 8 + 2 * cg;
                int ch  = isv ? col - 768 : col;
                int h   = ch >> 6;
                int d   = ch & 63;
                int i   = d >> 1;
                float c0 = cosb[t0 * 32 + i], s0 = sinb[t0 * 32 + i];
                float c1 = cosb[t1 * 32 + i], s1 = sinb[t1 * 32 + i];
                size_t o0 = ((size_t)(b * Hz + h) * Tz + t0) * Dz + d;
                size_t o1 = ((size_t)(b * Hz + h) * Tz + t1) * Dz + d;
                float v0 = acc[ma][na][0], v1 = acc[ma][na][1];
                float v2 = acc[ma][na][2], v3 = acc[ma][na][3];
                if (!isv) {
                    *reinterpret_cast<uint32_t*>(Kf + o0) =
                        packh2(v0 * c0 - v1 * s0, v0 * s0 + v1 * c0);
                    *reinterpret_cast<uint32_t*>(Kf + o1) =
                        packh2(v2 * c1 - v3 * s1, v2 * s1 + v3 * c1);
                } else {
                    *reinterpret_cast<uint32_t*>(Qf + o0) =
                        packh2((v0 * c0 - v1 * s0) * scale, (v0 * s0 + v1 * c0) * scale);
                    *reinterpret_cast<uint32_t*>(Qf + o1) =
                        packh2((v2 * c1 - v3 * s1) * scale, (v2 * s1 + v3 * c1) * scale);
                    *reinterpret_cast<uint32_t*>(Vf + o0) = packh2(v0, v1);
                    *reinterpret_cast<uint32_t*>(Vf + o1) = packh2(v2, v3);
                }
            }
        }
    }
}

// ---------------------------------------------------------------------------
// Flash attention v11: 4-stage cp.async KV ring, prefetch depth 2, block-wide
// barrier only on EVEN iterations (buffer written at jt was last read at
// jt-2; the even-jt barrier guarantees all warps are past jt-1 >= jt-2).
// exp2-domain softmax, MMA row-sums. 128 q-rows, 8 warps x 16 q-rows.
// ---------------------------------------------------------------------------
#define FX_STRIDE 144                 // 64 fp16 = 128B + 16B pad
#define FX_TILE   (128 * FX_STRIDE)   // 18432
#define FX_STAGE  (2 * FX_TILE)       // KF,VF = 36864
#define FX_Q      (4 * FX_STAGE)      // 147456
#define FX_SMEM   (FX_Q + FX_TILE)    // 165888 -> 1 CTA/SM

__global__ __launch_bounds__(256, 1) void flash11_kernel(
    const fp16* __restrict__ Qf, const fp16* __restrict__ Kf,
    const fp16* __restrict__ Vf, fp16* __restrict__ Of)
{
    extern __shared__ __align__(16) char smx[];
    const uint32_t smb = smem_u32(smx);
    const int tid  = threadIdx.x;
    const int w    = tid >> 5;
    const int lane = tid & 31;
    const int qt   = (int)gridDim.x - 1 - (int)blockIdx.x;   // heavy tiles first
    const int bh   = blockIdx.y;
    const size_t hb = (size_t)bh * Tz * Dz;
    const uint32_t ONES = 0x3C003C00u;   // fp16 {1,1}

    auto load_kv = [&](int s, int j) {
        uint32_t base = smb + s * FX_STAGE;
        const size_t kb = hb + (size_t)j * 128 * 64;
        #pragma unroll
        for (int it = 0; it < 4; it++) {
            int u = tid + it * 256;
            int row = u >> 3, cc = u & 7;
            uint32_t off = (uint32_t)(row * FX_STRIDE + cc * 16);
            size_t g = kb + row * 64 + cc * 8;
            cpa16(base + 0 * FX_TILE + off, Kf + g);
            cpa16(base + 1 * FX_TILE + off, Vf + g);
        }
    };

    load_kv(0, 0);
    CP_COMMIT();
    if (qt >= 1) load_kv(1, 1);
    CP_COMMIT();
    {
        const fp16* qsrc = Qf + hb + (size_t)qt * 128 * 64;
        #pragma unroll
        for (int it = 0; it < 4; it++) {
            int u = tid + it * 256;
            int row = u >> 3, cc = u & 7;
            *reinterpret_cast<uint4*>(smx + FX_Q + row * FX_STRIDE + cc * 16) =
                *reinterpret_cast<const uint4*>(qsrc + row * 64 + cc * 8);
        }
    }
    __syncthreads();

    uint32_t qf[16];
    {
        int arow = lane & 15, asel = lane >> 4;
        #pragma unroll
        for (int ka = 0; ka < 4; ka++)
            ldmx4(qf + ka * 4, smb + FX_Q +
                  (uint32_t)((16 * w + arow) * FX_STRIDE + ka * 32 + asel * 16));
    }

    float o[8][4];
    #pragma unroll
    for (int nv = 0; nv < 8; nv++)
        #pragma unroll
        for (int c = 0; c < 4; c++) o[nv][c] = 0.f;
    float mA = -1e30f, mB = -1e30f, lA = 0.f, lB = 0.f;

    const int rg = lane >> 2, cg = lane & 3;
    const int brow = lane & 7, bsel = (lane >> 3) & 3;
    const int vkey = lane & 15, vsel = lane >> 4;

    for (int jt = 0; jt <= qt; jt++) {
        CP_WAIT(1);                            // stage jt ready (per-warp)
        if ((jt & 1) == 0) __syncthreads();    // skew barrier every 2 iters
        if (jt + 2 <= qt) load_kv((jt + 2) & 3, jt + 2);
        CP_COMMIT();                           // uniform group numbering

        const uint32_t sb = smb + (jt & 3) * FX_STAGE;

        // ---- S = Q@K^T (log2 domain), single-pass fp16 ----
        float s[16][4];
        #pragma unroll
        for (int na = 0; na < 16; na++)
            #pragma unroll
            for (int c = 0; c < 4; c++) s[na][c] = 0.f;

        #pragma unroll
        for (int kp = 0; kp < 2; kp++) {
            #pragma unroll
            for (int half = 0; half < 2; half++) {
                uint32_t kf[8][4];
                #pragma unroll
                for (int q = 0; q < 8; q++)
                    ldmx4(kf[q], sb +
                          (uint32_t)(((half * 8 + q) * 8 + brow) * FX_STRIDE + kp * 64 + bsel * 16));
                #pragma unroll
                for (int j = 0; j < 2; j++)
                    #pragma unroll
                    for (int q = 0; q < 8; q++)
                        mma_f16(s[half * 8 + q], qf + (2 * kp + j) * 4, kf[q][2 * j], kf[q][2 * j + 1]);
            }
        }

        // ---- causal mask (diagonal tile) ----
        if (jt == qt) {
            int rA = 16 * w + rg, rB = rA + 8;
            #pragma unroll
            for (int na = 0; na < 16; na++) {
                int c0 = 8 * na + 2 * cg;
                if (c0 > rA)     s[na][0] = -1e30f;
                if (c0 + 1 > rA) s[na][1] = -1e30f;
                if (c0 > rB)     s[na][2] = -1e30f;
                if (c0 + 1 > rB) s[na][3] = -1e30f;
            }
        }

        // ---- online softmax: row maxes + rescale (log2 domain) ----
        float xA = -1e30f, xB = -1e30f;
        #pragma unroll
        for (int na = 0; na < 16; na++) {
            xA = fmaxf(xA, fmaxf(s[na][0], s[na][1]));
            xB = fmaxf(xB, fmaxf(s[na][2], s[na][3]));
        }
        xA = fmaxf(xA, __shfl_xor_sync(0xffffffffu, xA, 1));
        xA = fmaxf(xA, __shfl_xor_sync(0xffffffffu, xA, 2));
        xB = fmaxf(xB, __shfl_xor_sync(0xffffffffu, xB, 1));
        xB = fmaxf(xB, __shfl_xor_sync(0xffffffffu, xB, 2));
        float nmA = fmaxf(mA, xA), nmB = fmaxf(mB, xB);
        float cA = ex2(mA - nmA), cB = ex2(mB - nmB);
        mA = nmA; mB = nmB;
        #pragma unroll
        for (int nv = 0; nv < 8; nv++) {
            o[nv][0] *= cA; o[nv][1] *= cA;
            o[nv][2] *= cB; o[nv][3] *= cB;
        }

        // ---- PV: exp2 -> fp16 P; V mma; row-sums via ones-MMA ----
        float lacc[4] = {0.f, 0.f, 0.f, 0.f};
        #pragma unroll
        for (int ka = 0; ka < 8; ka++) {
            float e00 = ex2(s[2 * ka][0] - nmA);
            float e01 = ex2(s[2 * ka][1] - nmA);
            float e02 = ex2(s[2 * ka][2] - nmB);
            float e03 = ex2(s[2 * ka][3] - nmB);
            float e10 = ex2(s[2 * ka + 1][0] - nmA);
            float e11 = ex2(s[2 * ka + 1][1] - nmA);
            float e12 = ex2(s[2 * ka + 1][2] - nmB);
            float e13 = ex2(s[2 * ka + 1][3] - nmB);

            uint32_t p4[4];
            p4[0] = packh2(e00, e01);
            p4[1] = packh2(e02, e03);
            p4[2] = packh2(e10, e11);
            p4[3] = packh2(e12, e13);

            mma_f16(lacc, p4, ONES, ONES);   // row sums of quantized P

            uint32_t vf[4][4];
            #pragma unroll
            for (int nv = 0; nv < 4; nv++)
                ldmx4t(vf[nv], sb + 1 * FX_TILE +
                       (uint32_t)((ka * 16 + vkey) * FX_STRIDE + (nv * 16 + vsel * 8) * 2));
            #pragma unroll
            for (int nv = 0; nv < 4; nv++) {
                mma_f16(o[2 * nv],     p4, vf[nv][0], vf[nv][1]);
                mma_f16(o[2 * nv + 1], p4, vf[nv][2], vf[nv][3]);
            }
        }
        lA = lA * cA + lacc[0];
        lB = lB * cB + lacc[2];
    }

    // ---- normalize + write fp16 [B,T,C] ----
    const int b = bh / Hz, h = bh % Hz;
    const float invA = 1.f / lA, invB = 1.f / lB;
    int rA = qt * 128 + 16 * w + rg;
    #pragma unroll
    for (int nv = 0; nv < 8; nv++) {
        int col = h * 64 + nv * 8 + 2 * cg;
        size_t baseA = (size_t)(b * Tz + rA) * Cz + col;
        size_t baseB = (size_t)(b * Tz + rA + 8) * Cz + col;
        *reinterpret_cast<uint32_t*>(Of + baseA) =
            packh2(o[nv][0] * invA, o[nv][1] * invA);
        *reinterpret_cast<uint32_t*>(Of + baseB) =
            packh2(o[nv][2] * invB, o[nv][3] * invB);
    }
}

// ---------------------------------------------------------------------------
// kernel_launch
// ---------------------------------------------------------------------------
extern "C" void kernel_launch(void* const* d_in, const int* in_sizes, int n_in,
                              void* d_out, int out_size)
{
    const float* x      = (const float*)d_in[0];
    const float* cosb   = (const float*)d_in[1];
    const float* sinb   = (const float*)d_in[2];
    const float* W_att  = (const float*)d_in[3];
    const float* W_proj = (const float*)d_in[4];
    const float* b_proj = (const float*)d_in[5];
    float* out = (float*)d_out;

    fp16 *xf, *af, *w1, *w2, *Kfp, *Qfp, *Vfp;
    cudaGetSymbolAddress((void**)&xf,  g_xf);
    cudaGetSymbolAddress((void**)&af,  g_af);
    cudaGetSymbolAddress((void**)&w1,  g_w1);
    cudaGetSymbolAddress((void**)&w2,  g_w2);
    cudaGetSymbolAddress((void**)&Kfp, g_Kf);
    cudaGetSymbolAddress((void**)&Qfp, g_Qf);
    cudaGetSymbolAddress((void**)&Vfp, g_Vf);

    cudaFuncSetAttribute(mm_gemm_kernel<0>,
                         cudaFuncAttributeMaxDynamicSharedMemorySize, MG_SMEM);
    cudaFuncSetAttribute(mm_gemm_kernel<1>,
                         cudaFuncAttributeMaxDynamicSharedMemorySize, MG_SMEM);
    cudaFuncSetAttribute(flash11_kernel,
                         cudaFuncAttributeMaxDynamicSharedMemorySize, FX_SMEM);

    // prep: merged x-conv + weight transposes (one launch)
    prep_kernel<<<dim3(48, Cz / 32, 3), 256>>>(x, xf, W_att, w1, W_proj, w2);

    // 1) QKV GEMM + fused RoPE epilogue -> Kf / Qf / Vf  [BH,T,D]
    mm_gemm_kernel<1><<<dim3(1536 / 128, Mz / 128), 256, MG_SMEM>>>(
        xf, w1, nullptr, nullptr, cosb, sinb, Kfp, Qfp, Vfp, Cz, 0);

    // 2) Flash attention (4-stage ring, barrier every other iter) -> af fp16
    flash11_kernel<<<dim3(Tz / 128, BHz), 256, FX_SMEM>>>(
        Qfp, Kfp, Vfp, af);

    // 3) proj GEMM + bias -> d_out  (128x128 tiles — round-15 known-good)
    mm_gemm_kernel<0><<<dim3(Cz / 128, Mz / 128), 256, MG_SMEM>>>(
        af, w2, out, b_proj, nullptr, nullptr,
        nullptr, nullptr, nullptr, Cz, Cz);
}